// round 13
// baseline (speedup 1.0000x reference)
#include <cuda_runtime.h>
#include <cuda_fp16.h>
#include <cstdint>

#define TT   4
#define HH   48
#define WWD  48
#define PP   2304          // 48*48
#define R5   6400          // 256*25
#define R3   6912          // 256*27
#define RF   13312         // R5 + R3 fused K
#define OFFC 200           // 4*2*25

typedef __half fp16;

// ---------------- scratch (static device globals; no allocation) ----------------
__device__ fp16 g_xT[(size_t)TT * PP * 256];  // [t][p][c] fp16 transpose of x (L2-resident)
__device__ fp16 g_Bs[(size_t)TT * PP * R5];   // [t][p][k*256+c] sampled B (k-major)
__device__ fp16 g_Woff_h[256 * R5];           // [o][k*256+c]
__device__ fp16 g_Wf_h[256 * RF];             // [o][r] k-major both halves
__device__ float g_off[TT * OFFC * PP];       // [t][och][p]

// ---------------- side stream: LAZY init on first kernel_launch (never in static ctor —
// pre-main CUDA calls latch error 802 "system not yet initialized" on GB300) ----------------
static cudaStream_t g_side = nullptr;
static cudaEvent_t g_fork, g_e1, g_e2;

// ---------------- helpers ----------------
__device__ __forceinline__ uint32_t smem_u32(const void* p) {
    uint32_t a;
    asm("{ .reg .u64 t; cvta.to.shared.u64 t, %1; cvt.u32.u64 %0, t; }" : "=r"(a) : "l"(p));
    return a;
}
__device__ __forceinline__ void cpa16(uint32_t dst, const void* src) {
    asm volatile("cp.async.cg.shared.global [%0], [%1], 16;" :: "r"(dst), "l"(src) : "memory");
}
__device__ __forceinline__ void cpa16z(uint32_t dst, const void* src, int vld16) {
    asm volatile("cp.async.cg.shared.global [%0], [%1], 16, %2;"
                 :: "r"(dst), "l"(src), "r"(vld16) : "memory");
}
__device__ __forceinline__ void ldsm4(uint32_t* r, uint32_t a) {
    asm volatile("ldmatrix.sync.aligned.m8n8.x4.shared.b16 {%0,%1,%2,%3}, [%4];"
                 : "=r"(r[0]), "=r"(r[1]), "=r"(r[2]), "=r"(r[3]) : "r"(a));
}
__device__ __forceinline__ void mma16816(float* c, const uint32_t* a, const uint32_t* b) {
    asm volatile("mma.sync.aligned.m16n8k16.row.col.f32.f16.f16.f32 "
                 "{%0,%1,%2,%3}, {%4,%5,%6,%7}, {%8,%9}, {%0,%1,%2,%3};"
                 : "+f"(c[0]), "+f"(c[1]), "+f"(c[2]), "+f"(c[3])
                 : "r"(a[0]), "r"(a[1]), "r"(a[2]), "r"(a[3]), "r"(b[0]), "r"(b[1]));
}

// ---------------- x transpose: x[c][t][p] fp32 -> xT[t][p][c] fp16 ----------------
__global__ void __launch_bounds__(256) transpose_x(const float* __restrict__ x,
                                                   fp16* __restrict__ xT) {
    __shared__ float tl[32][33];
    int t = blockIdx.x, p0 = blockIdx.y * 32, c0 = blockIdx.z * 32;
    int tx = threadIdx.x & 31, ty = threadIdx.x >> 5;
    #pragma unroll
    for (int i = ty; i < 32; i += 8)
        tl[i][tx] = x[((size_t)(c0 + i) * TT + t) * PP + p0 + tx];
    __syncthreads();
    #pragma unroll
    for (int i = ty; i < 32; i += 8)
        xT[((size_t)t * PP + p0 + i) * 256 + c0 + tx] = __float2half_rn(tl[tx][i]);
}

// ---------------- weight pack (offset): w_off[o][c][k] -> [o][k*256+c], pad O ----------------
__global__ void packw_off(const float* __restrict__ src, fp16* __restrict__ h) {
    int o = blockIdx.x;
    int r = blockIdx.y * 256 + threadIdx.x;     // r = k*256 + c
    int c = r & 255, k = r >> 8;
    float v = (o < OFFC) ? src[((size_t)o * 256 + c) * 25 + k] : 0.0f;
    h[(size_t)o * R5 + r] = __float2half_rn(v);
}

// ---------------- weight pack (fused): [w_def | w_temp] k-major over RF ----------------
__global__ void packw_f(const float* __restrict__ wdef, const float* __restrict__ wtmp,
                        fp16* __restrict__ h) {
    int o = blockIdx.x;
    int r = blockIdx.y * 256 + threadIdx.x;
    float v;
    if (r < R5) {
        int c = r & 255, k = r >> 8;
        v = wdef[((size_t)o * 256 + c) * 25 + k];
    } else {
        int m = r - R5;
        int c = m & 255, q = m >> 8;
        v = wtmp[((size_t)o * 256 + c) * 27 + q];
    }
    h[(size_t)o * RF + r] = __float2half_rn(v);
}

// ---------------- bilinear sampler on xT -> Bs[t][p][k*256+c] ----------------
__global__ void __launch_bounds__(256) sample_k(const fp16* __restrict__ xT,
                                                const float* __restrict__ off,
                                                fp16* __restrict__ Bs) {
    int t = blockIdx.x, p0 = blockIdx.y * 32, dg = blockIdx.z;
    int oct = threadIdx.x & 7, pl = threadIdx.x >> 3;
    int p = p0 + pl, py = p / WWD, px = p % WWD;
    const fp16* xb = xT + (size_t)t * PP * 256 + dg * 64 + oct * 8;
    fp16* dstb = Bs + ((size_t)t * PP + p) * R5 + dg * 64 + oct * 8;
    #pragma unroll 1
    for (int k = 0; k < 25; k++) {
        const float* offy = off + ((size_t)t * OFFC + (dg * 25 + k) * 2) * PP;
        float sy = (float)(py + k / 5 - 2) + __ldg(offy + p);
        float sx = (float)(px + k % 5 - 2) + __ldg(offy + PP + p);
        float fy = floorf(sy), fx = floorf(sx);
        int y0 = (int)fy, x0 = (int)fx;
        float wy = sy - fy, wx = sx - fx;
        int y1 = y0 + 1, x1 = x0 + 1;
        float vy0 = (y0 >= 0 && y0 < HH) ? 1.0f : 0.0f;
        float vy1 = (y1 >= 0 && y1 < HH) ? 1.0f : 0.0f;
        float vx0 = (x0 >= 0 && x0 < WWD) ? 1.0f : 0.0f;
        float vx1 = (x1 >= 0 && x1 < WWD) ? 1.0f : 0.0f;
        int y0c = min(max(y0, 0), HH - 1), y1c = min(max(y1, 0), HH - 1);
        int x0c = min(max(x0, 0), WWD - 1), x1c = min(max(x1, 0), WWD - 1);
        float w00 = (1.0f - wy) * (1.0f - wx) * vy0 * vx0;
        float w01 = (1.0f - wy) * wx          * vy0 * vx1;
        float w10 = wy          * (1.0f - wx) * vy1 * vx0;
        float w11 = wy          * wx          * vy1 * vx1;
        const __half2* a = (const __half2*)(xb + (size_t)(y0c * WWD + x0c) * 256);
        const __half2* b = (const __half2*)(xb + (size_t)(y0c * WWD + x1c) * 256);
        const __half2* cq = (const __half2*)(xb + (size_t)(y1c * WWD + x0c) * 256);
        const __half2* d = (const __half2*)(xb + (size_t)(y1c * WWD + x1c) * 256);
        __half2 r[4];
        #pragma unroll
        for (int j = 0; j < 4; j++) {
            float2 fa = __half22float2(a[j]), fb = __half22float2(b[j]);
            float2 fc = __half22float2(cq[j]), fd = __half22float2(d[j]);
            float rx = w00 * fa.x + w01 * fb.x + w10 * fc.x + w11 * fd.x;
            float ry = w00 * fa.y + w01 * fb.y + w10 * fc.y + w11 * fd.y;
            r[j] = __floats2half2_rn(rx, ry);
        }
        *(uint4*)(dstb + k * 256) = *(uint4*)r;
    }
}

// ---------------- GEMM: tile 128(o) x 128(p), 8 warps, intra-CTA K-split ----------------
// Warp-groups: wg0 does kk 0-1, wg1 does kk 2-3 of each K-chunk, private accs;
// final smem reduction by wg1. Warp tile 64x64 (MMA:LDSM stays 4.0), 2 warps/SMSP.
// K chunk 64, 4 stages (32KB each = 128KB).
// MODE 0: offset conv — B fully implicit 1x5x5 from xT.
// MODE 1: fused — chunks <100 explicit from Bs, >=100 implicit 3x3x3 from xT.
#define NSTAGE 4
#define STG    32768
#define GSMEM  (NSTAGE * STG)

template<int MODE>
__device__ __forceinline__ void loadB_chunk(
    uint32_t dstB, int ch, int t, const fp16* __restrict__ BsRow,
    const fp16* __restrict__ xT, int c8, int rb,
    const int* pj, const int* pyj, const int* pxj)
{
    if (MODE == 1 && ch < 100) {
        size_t rof = (size_t)ch * 64 + c8 * 8;
        #pragma unroll
        for (int j = 0; j < 4; j++) {
            int row = rb + 32 * j;
            cpa16(dstB + row * 128 + ((c8 ^ (row & 7)) << 4),
                  BsRow + (size_t)row * R5 + rof);
        }
    } else {
        int m = (MODE == 1) ? ch - 100 : ch;
        int kk = m >> 2, c0 = (m & 3) * 64;
        int dy, dx, tt;
        if (MODE == 0) { dy = kk / 5 - 2; dx = kk % 5 - 2; tt = t; }
        else { tt = t + kk / 9 - 1; int rq = kk % 9; dy = rq / 3 - 1; dx = rq % 3 - 1; }
        int tok = (tt >= 0 && tt < TT) ? 1 : 0;
        #pragma unroll
        for (int j = 0; j < 4; j++) {
            int row = rb + 32 * j;
            int y = pyj[j] + dy, x = pxj[j] + dx;
            int vld = (tok && y >= 0 && y < HH && x >= 0 && x < WWD) ? 16 : 0;
            size_t soff = vld ? ((size_t)(tt * PP + pj[j] + dy * WWD + dx) * 256
                                 + c0 + c8 * 8) : 0;
            cpa16z(dstB + row * 128 + ((c8 ^ (row & 7)) << 4), xT + soff, vld);
        }
    }
}

template<int MODE>
__global__ void __launch_bounds__(256, 1) gemm_mma(
    const fp16* __restrict__ Wh, const fp16* __restrict__ Bs,
    const fp16* __restrict__ xT,
    float* __restrict__ outp, int R, int Olim,
    long long o_stride, long long t_stride,
    const float* __restrict__ bias)
{
    extern __shared__ char smraw[];
    uint32_t sb = smem_u32(smraw);
    int tid = threadIdx.x, lane = tid & 31, wid = tid >> 5;
    int wg = wid >> 2, w4 = wid & 3;
    int wm = w4 & 1, wn = w4 >> 1;                 // 2 x 2 -> warp tile 64(m) x 64(n)
    int p0 = blockIdx.x * 128, t = blockIdx.y, o0 = blockIdx.z * 128;

    const fp16* gA = Wh + (size_t)o0 * R;
    const fp16* BsRow = Bs + ((size_t)t * PP + p0) * R5;

    int c8 = tid & 7;
    int rb = tid >> 3;             // 0..31
    int NC = R >> 6;

    int pj[4], pyj[4], pxj[4];
    #pragma unroll
    for (int j = 0; j < 4; j++) {
        pj[j] = p0 + rb + 32 * j;
        pyj[j] = pj[j] / WWD;
        pxj[j] = pj[j] % WWD;
    }

    int aRow = (lane & 7) + ((lane >> 3) & 1) * 8;
    int aKg  = (lane >> 4) & 1;
    int bRow = (lane & 7) + ((lane >> 4) & 1) * 8;
    int bKg  = (lane >> 3) & 1;

    float acc[4][8][4];
    #pragma unroll
    for (int i = 0; i < 4; i++)
        #pragma unroll
        for (int j = 0; j < 8; j++)
            #pragma unroll
            for (int q = 0; q < 4; q++) acc[i][j][q] = 0.0f;

    // prologue: chunks 0..2
    #pragma unroll
    for (int pc = 0; pc < NSTAGE - 1; pc++) {
        uint32_t stb = sb + pc * STG;
        size_t rof = (size_t)(pc * 64) + c8 * 8;
        #pragma unroll
        for (int j = 0; j < 4; j++) {
            int row = rb + 32 * j;
            cpa16(stb + row * 128 + ((c8 ^ (row & 7)) << 4), gA + (size_t)row * R + rof);
        }
        loadB_chunk<MODE>(stb + 16384, pc, t, BsRow, xT, c8, rb, pj, pyj, pxj);
        asm volatile("cp.async.commit_group;" ::: "memory");
    }

    for (int ch = 0; ch < NC; ch++) {
        asm volatile("cp.async.wait_group 2;" ::: "memory");
        __syncthreads();
        uint32_t stb = sb + (ch % NSTAGE) * STG;

        // K-split: wg0 -> kk 0,1 ; wg1 -> kk 2,3
        #pragma unroll
        for (int ks = 0; ks < 2; ks++) {
            int kk = wg * 2 + ks;
            uint32_t ah[4][4], bh[8][2];
            #pragma unroll
            for (int mt = 0; mt < 4; mt++) {
                int row = wm * 64 + mt * 16 + aRow;
                ldsm4(ah[mt], stb + row * 128 + (((kk * 2 + aKg) ^ (row & 7)) << 4));
            }
            #pragma unroll
            for (int ng = 0; ng < 4; ng++) {
                int row = wn * 64 + ng * 16 + bRow;
                uint32_t r4[4];
                ldsm4(r4, stb + 16384 + row * 128 + (((kk * 2 + bKg) ^ (row & 7)) << 4));
                bh[ng * 2][0] = r4[0]; bh[ng * 2][1] = r4[1];
                bh[ng * 2 + 1][0] = r4[2]; bh[ng * 2 + 1][1] = r4[3];
            }
            #pragma unroll
            for (int mt = 0; mt < 4; mt++)
                #pragma unroll
                for (int nt = 0; nt < 8; nt++)
                    mma16816(acc[mt][nt], ah[mt], bh[nt]);
        }

        int nx = ch + NSTAGE - 1;
        if (nx < NC) {
            uint32_t stb2 = sb + (nx % NSTAGE) * STG;
            size_t rof = (size_t)nx * 64 + c8 * 8;
            #pragma unroll
            for (int j = 0; j < 4; j++) {
                int row = rb + 32 * j;
                cpa16(stb2 + row * 128 + ((c8 ^ (row & 7)) << 4), gA + (size_t)row * R + rof);
            }
            loadB_chunk<MODE>(stb2 + 16384, nx, t, BsRow, xT, c8, rb, pj, pyj, pxj);
        }
        asm volatile("cp.async.commit_group;" ::: "memory");
    }

    // reduce wg0's accumulators into wg1 via (now dead) stage smem, then epilogue by wg1
    float* red = (float*)smraw;
    int rbase = w4 * 4096;         // 4 warps x 4096 floats = 64KB
    __syncthreads();
    if (wg == 0) {
        #pragma unroll
        for (int mt = 0; mt < 4; mt++)
            #pragma unroll
            for (int nt = 0; nt < 8; nt++)
                #pragma unroll
                for (int q = 0; q < 4; q++)
                    red[rbase + ((mt * 8 + nt) * 4 + q) * 32 + lane] = acc[mt][nt][q];
    }
    __syncthreads();
    if (wg == 1) {
        int er = lane >> 2, ec = (lane & 3) * 2;
        #pragma unroll
        for (int mt = 0; mt < 4; mt++) {
            int obase = o0 + wm * 64 + mt * 16 + er;
            #pragma unroll
            for (int nt = 0; nt < 8; nt++)
                #pragma unroll
                for (int q = 0; q < 4; q++)
                    acc[mt][nt][q] += red[rbase + ((mt * 8 + nt) * 4 + q) * 32 + lane];
            #pragma unroll
            for (int h = 0; h < 2; h++) {
                int o = obase + h * 8;
                if (o < Olim) {
                    float bv = (bias != nullptr) ? bias[o] : 0.0f;
                    size_t rb2 = (size_t)o * o_stride + (size_t)t * t_stride + p0 + wn * 64 + ec;
                    #pragma unroll
                    for (int nt = 0; nt < 8; nt++) {
                        float2* dp = (float2*)(outp + rb2 + nt * 8);
                        float2 wv;
                        wv.x = acc[mt][nt][h * 2 + 0] + bv;
                        wv.y = acc[mt][nt][h * 2 + 1] + bv;
                        *dp = wv;
                    }
                }
            }
        }
    }
}

// ---------------- launch ----------------
extern "C" void kernel_launch(void* const* d_in, const int* in_sizes, int n_in,
                              void* d_out, int out_size) {
    (void)in_sizes; (void)n_in; (void)out_size;
    const float* x      = (const float*)d_in[0];
    const float* w_off  = (const float*)d_in[1];
    const float* w_def  = (const float*)d_in[2];
    const float* w_temp = (const float*)d_in[3];
    const float* b_temp = (const float*)d_in[4];
    float* out = (float*)d_out;

    // Lazy one-time init (first call is the uncaptured correctness run).
    if (g_side == nullptr) {
        cudaStreamCreateWithFlags(&g_side, cudaStreamNonBlocking);
        cudaEventCreateWithFlags(&g_fork, cudaEventDisableTiming);
        cudaEventCreateWithFlags(&g_e1, cudaEventDisableTiming);
        cudaEventCreateWithFlags(&g_e2, cudaEventDisableTiming);
        cudaFuncSetAttribute(gemm_mma<0>, cudaFuncAttributeMaxDynamicSharedMemorySize, GSMEM);
        cudaFuncSetAttribute(gemm_mma<1>, cudaFuncAttributeMaxDynamicSharedMemorySize, GSMEM);
    }

    fp16 *xTp, *Bsp, *wofh, *wfh;
    float* offp;
    cudaGetSymbolAddress((void**)&xTp,  g_xT);
    cudaGetSymbolAddress((void**)&Bsp,  g_Bs);
    cudaGetSymbolAddress((void**)&wofh, g_Woff_h);
    cudaGetSymbolAddress((void**)&wfh,  g_Wf_h);
    cudaGetSymbolAddress((void**)&offp, g_off);

    // fork: weight packs on side stream
    cudaEventRecord(g_fork, 0);
    cudaStreamWaitEvent(g_side, g_fork, 0);
    packw_off<<<dim3(256, 25), 256, 0, g_side>>>(w_off, wofh);
    cudaEventRecord(g_e1, g_side);
    packw_f<<<dim3(256, 52), 256, 0, g_side>>>(w_def, w_temp, wfh);
    cudaEventRecord(g_e2, g_side);

    // main: transpose -> offset GEMM (implicit B) -> sampler -> fused GEMM
    transpose_x<<<dim3(TT, 72, 8), 256>>>(x, xTp);
    cudaStreamWaitEvent(0, g_e1, 0);
    gemm_mma<0><<<dim3(18, TT, 2), 256, GSMEM>>>(
        wofh, xTp /*unused explicit*/, xTp, offp, R5, OFFC,
        PP, (long long)OFFC * PP, nullptr);

    sample_k<<<dim3(TT, 72, 4), 256>>>(xTp, offp, Bsp);

    cudaStreamWaitEvent(0, g_e2, 0);
    gemm_mma<1><<<dim3(18, TT, 2), 256, GSMEM>>>(
        wfh, Bsp, xTp, out, RF, 256, (long long)TT * PP, PP, b_temp);
}

// round 14
// speedup vs baseline: 1.0528x; 1.0528x over previous
#include <cuda_runtime.h>
#include <cuda_fp16.h>
#include <cstdint>

#define TT   4
#define HH   48
#define WWD  48
#define PP   2304          // 48*48
#define R5   6400          // 256*25
#define R3   6912          // 256*27
#define RF   13312         // R5 + R3 fused K
#define OFFC 200           // 4*2*25

typedef __half fp16;

// ---------------- scratch (static device globals; no allocation) ----------------
__device__ fp16 g_xT[(size_t)TT * PP * 256];  // [t][p][c] fp16 transpose of x (L2-resident)
__device__ fp16 g_Bs[(size_t)TT * PP * R5];   // [t][p][k*256+c] sampled B (k-major)
__device__ fp16 g_Woff_h[256 * R5];           // [o][k*256+c]
__device__ fp16 g_Wf_h[256 * RF];             // [o][r] k-major both halves
__device__ float g_off[TT * OFFC * PP];       // [t][och][p]

// ---------------- side stream: LAZY init on first kernel_launch (never in static ctor —
// pre-main CUDA calls latch error 802 "system not yet initialized" on GB300) ----------------
static cudaStream_t g_side = nullptr;
static cudaEvent_t g_fork, g_e1, g_e2;

// ---------------- helpers ----------------
__device__ __forceinline__ uint32_t smem_u32(const void* p) {
    uint32_t a;
    asm("{ .reg .u64 t; cvta.to.shared.u64 t, %1; cvt.u32.u64 %0, t; }" : "=r"(a) : "l"(p));
    return a;
}
__device__ __forceinline__ void cpa16(uint32_t dst, const void* src) {
    asm volatile("cp.async.cg.shared.global [%0], [%1], 16;" :: "r"(dst), "l"(src) : "memory");
}
__device__ __forceinline__ void cpa16z(uint32_t dst, const void* src, int vld16) {
    asm volatile("cp.async.cg.shared.global [%0], [%1], 16, %2;"
                 :: "r"(dst), "l"(src), "r"(vld16) : "memory");
}
__device__ __forceinline__ void ldsm4(uint32_t* r, uint32_t a) {
    asm volatile("ldmatrix.sync.aligned.m8n8.x4.shared.b16 {%0,%1,%2,%3}, [%4];"
                 : "=r"(r[0]), "=r"(r[1]), "=r"(r[2]), "=r"(r[3]) : "r"(a));
}
__device__ __forceinline__ void mma16816(float* c, const uint32_t* a, const uint32_t* b) {
    asm volatile("mma.sync.aligned.m16n8k16.row.col.f32.f16.f16.f32 "
                 "{%0,%1,%2,%3}, {%4,%5,%6,%7}, {%8,%9}, {%0,%1,%2,%3};"
                 : "+f"(c[0]), "+f"(c[1]), "+f"(c[2]), "+f"(c[3])
                 : "r"(a[0]), "r"(a[1]), "r"(a[2]), "r"(a[3]), "r"(b[0]), "r"(b[1]));
}

// ---------------- x transpose: x[c][t][p] fp32 -> xT[t][p][c] fp16 ----------------
__global__ void __launch_bounds__(256) transpose_x(const float* __restrict__ x,
                                                   fp16* __restrict__ xT) {
    __shared__ float tl[32][33];
    int t = blockIdx.x, p0 = blockIdx.y * 32, c0 = blockIdx.z * 32;
    int tx = threadIdx.x & 31, ty = threadIdx.x >> 5;
    #pragma unroll
    for (int i = ty; i < 32; i += 8)
        tl[i][tx] = x[((size_t)(c0 + i) * TT + t) * PP + p0 + tx];
    __syncthreads();
    #pragma unroll
    for (int i = ty; i < 32; i += 8)
        xT[((size_t)t * PP + p0 + i) * 256 + c0 + tx] = __float2half_rn(tl[tx][i]);
}

// ---------------- weight pack (offset): w_off[o][c][k] -> [o][k*256+c], pad O ----------------
__global__ void packw_off(const float* __restrict__ src, fp16* __restrict__ h) {
    int o = blockIdx.x;
    int r = blockIdx.y * 256 + threadIdx.x;     // r = k*256 + c
    int c = r & 255, k = r >> 8;
    float v = (o < OFFC) ? src[((size_t)o * 256 + c) * 25 + k] : 0.0f;
    h[(size_t)o * R5 + r] = __float2half_rn(v);
}

// ---------------- weight pack (fused): [w_def | w_temp] k-major over RF ----------------
__global__ void packw_f(const float* __restrict__ wdef, const float* __restrict__ wtmp,
                        fp16* __restrict__ h) {
    int o = blockIdx.x;
    int r = blockIdx.y * 256 + threadIdx.x;
    float v;
    if (r < R5) {
        int c = r & 255, k = r >> 8;
        v = wdef[((size_t)o * 256 + c) * 25 + k];
    } else {
        int m = r - R5;
        int c = m & 255, q = m >> 8;
        v = wtmp[((size_t)o * 256 + c) * 27 + q];
    }
    h[(size_t)o * RF + r] = __float2half_rn(v);
}

// ---------------- bilinear sampler on xT -> Bs[t][p][k*256+c] ----------------
__global__ void __launch_bounds__(256) sample_k(const fp16* __restrict__ xT,
                                                const float* __restrict__ off,
                                                fp16* __restrict__ Bs) {
    int t = blockIdx.x, p0 = blockIdx.y * 32, dg = blockIdx.z;
    int oct = threadIdx.x & 7, pl = threadIdx.x >> 3;
    int p = p0 + pl, py = p / WWD, px = p % WWD;
    const fp16* xb = xT + (size_t)t * PP * 256 + dg * 64 + oct * 8;
    fp16* dstb = Bs + ((size_t)t * PP + p) * R5 + dg * 64 + oct * 8;
    #pragma unroll 1
    for (int k = 0; k < 25; k++) {
        const float* offy = off + ((size_t)t * OFFC + (dg * 25 + k) * 2) * PP;
        float sy = (float)(py + k / 5 - 2) + __ldg(offy + p);
        float sx = (float)(px + k % 5 - 2) + __ldg(offy + PP + p);
        float fy = floorf(sy), fx = floorf(sx);
        int y0 = (int)fy, x0 = (int)fx;
        float wy = sy - fy, wx = sx - fx;
        int y1 = y0 + 1, x1 = x0 + 1;
        float vy0 = (y0 >= 0 && y0 < HH) ? 1.0f : 0.0f;
        float vy1 = (y1 >= 0 && y1 < HH) ? 1.0f : 0.0f;
        float vx0 = (x0 >= 0 && x0 < WWD) ? 1.0f : 0.0f;
        float vx1 = (x1 >= 0 && x1 < WWD) ? 1.0f : 0.0f;
        int y0c = min(max(y0, 0), HH - 1), y1c = min(max(y1, 0), HH - 1);
        int x0c = min(max(x0, 0), WWD - 1), x1c = min(max(x1, 0), WWD - 1);
        float w00 = (1.0f - wy) * (1.0f - wx) * vy0 * vx0;
        float w01 = (1.0f - wy) * wx          * vy0 * vx1;
        float w10 = wy          * (1.0f - wx) * vy1 * vx0;
        float w11 = wy          * wx          * vy1 * vx1;
        const __half2* a = (const __half2*)(xb + (size_t)(y0c * WWD + x0c) * 256);
        const __half2* b = (const __half2*)(xb + (size_t)(y0c * WWD + x1c) * 256);
        const __half2* cq = (const __half2*)(xb + (size_t)(y1c * WWD + x0c) * 256);
        const __half2* d = (const __half2*)(xb + (size_t)(y1c * WWD + x1c) * 256);
        __half2 r[4];
        #pragma unroll
        for (int j = 0; j < 4; j++) {
            float2 fa = __half22float2(a[j]), fb = __half22float2(b[j]);
            float2 fc = __half22float2(cq[j]), fd = __half22float2(d[j]);
            float rx = w00 * fa.x + w01 * fb.x + w10 * fc.x + w11 * fd.x;
            float ry = w00 * fa.y + w01 * fb.y + w10 * fc.y + w11 * fd.y;
            r[j] = __floats2half2_rn(rx, ry);
        }
        *(uint4*)(dstb + k * 256) = *(uint4*)r;
    }
}

// ---------------- GEMM: tile 128(o) x 128(p), 4 warps, warp tile 64x64 ----------------
// K chunk 128 = two 64-K sub-tiles per stage (A0,A1,B0,B1 = 64KB/stage), 3 stages (192KB).
// Sub-tile layout/swizzle identical to R12 (128B rows, col ^ (row&7)).
// MODE 0: offset conv — B fully implicit 1x5x5 from xT.
// MODE 1: fused — 64-sub-chunks <100 explicit from Bs, >=100 implicit 3x3x3 from xT.
#define NSTAGE 3
#define STG    65536
#define GSMEM  (NSTAGE * STG)

// load one 64-K sub-chunk of B (sub-chunk index m64, dst = that half's B base)
template<int MODE>
__device__ __forceinline__ void loadB64(
    uint32_t dstB, int m64, int t, const fp16* __restrict__ BsRow,
    const fp16* __restrict__ xT, int c8, int rb,
    const int* pj, const int* pyj, const int* pxj)
{
    if (MODE == 1 && m64 < 100) {
        size_t rof = (size_t)m64 * 64 + c8 * 8;
        #pragma unroll
        for (int j = 0; j < 8; j++) {
            int row = rb + 16 * j;
            cpa16(dstB + row * 128 + ((c8 ^ (row & 7)) << 4),
                  BsRow + (size_t)row * R5 + rof);
        }
    } else {
        int m = (MODE == 1) ? m64 - 100 : m64;
        int kk = m >> 2, c0 = (m & 3) * 64;
        int dy, dx, tt;
        if (MODE == 0) { dy = kk / 5 - 2; dx = kk % 5 - 2; tt = t; }
        else { tt = t + kk / 9 - 1; int rq = kk % 9; dy = rq / 3 - 1; dx = rq % 3 - 1; }
        int tok = (tt >= 0 && tt < TT) ? 1 : 0;
        #pragma unroll
        for (int j = 0; j < 8; j++) {
            int row = rb + 16 * j;
            int y = pyj[j] + dy, x = pxj[j] + dx;
            int vld = (tok && y >= 0 && y < HH && x >= 0 && x < WWD) ? 16 : 0;
            size_t soff = vld ? ((size_t)(tt * PP + pj[j] + dy * WWD + dx) * 256
                                 + c0 + c8 * 8) : 0;
            cpa16z(dstB + row * 128 + ((c8 ^ (row & 7)) << 4), xT + soff, vld);
        }
    }
}

template<int MODE>
__device__ __forceinline__ void load_chunk128(
    uint32_t stb, int ch, int t, const fp16* __restrict__ gA,
    const fp16* __restrict__ BsRow, const fp16* __restrict__ xT,
    int R, int c8, int rb, const int* pj, const int* pyj, const int* pxj)
{
    #pragma unroll
    for (int sub = 0; sub < 2; sub++) {
        int m64 = ch * 2 + sub;
        size_t rof = (size_t)m64 * 64 + c8 * 8;
        uint32_t sA = stb + sub * 16384;
        #pragma unroll
        for (int j = 0; j < 8; j++) {
            int row = rb + 16 * j;
            cpa16(sA + row * 128 + ((c8 ^ (row & 7)) << 4), gA + (size_t)row * R + rof);
        }
        loadB64<MODE>(stb + 32768 + sub * 16384, m64, t, BsRow, xT, c8, rb, pj, pyj, pxj);
    }
}

template<int MODE>
__global__ void __launch_bounds__(128, 1) gemm_mma(
    const fp16* __restrict__ Wh, const fp16* __restrict__ Bs,
    const fp16* __restrict__ xT,
    float* __restrict__ outp, int R, int Olim,
    long long o_stride, long long t_stride,
    const float* __restrict__ bias)
{
    extern __shared__ char smraw[];
    uint32_t sb = smem_u32(smraw);
    int tid = threadIdx.x, lane = tid & 31, wid = tid >> 5;
    int wm = wid & 1, wn = wid >> 1;               // 2 x 2 -> warp tile 64(m) x 64(n)
    int p0 = blockIdx.x * 128, t = blockIdx.y, o0 = blockIdx.z * 128;

    const fp16* gA = Wh + (size_t)o0 * R;
    const fp16* BsRow = Bs + ((size_t)t * PP + p0) * R5;

    int c8 = tid & 7;
    int rb = tid >> 3;             // 0..15
    int NC = R >> 7;               // 128-K chunks

    int pj[8], pyj[8], pxj[8];
    #pragma unroll
    for (int j = 0; j < 8; j++) {
        pj[j] = p0 + rb + 16 * j;
        pyj[j] = pj[j] / WWD;
        pxj[j] = pj[j] % WWD;
    }

    int aRow = (lane & 7) + ((lane >> 3) & 1) * 8;
    int aKg  = (lane >> 4) & 1;
    int bRow = (lane & 7) + ((lane >> 4) & 1) * 8;
    int bKg  = (lane >> 3) & 1;

    float acc[4][8][4];
    #pragma unroll
    for (int i = 0; i < 4; i++)
        #pragma unroll
        for (int j = 0; j < 8; j++)
            #pragma unroll
            for (int q = 0; q < 4; q++) acc[i][j][q] = 0.0f;

    // prologue: chunks 0,1
    #pragma unroll
    for (int pc = 0; pc < NSTAGE - 1; pc++) {
        load_chunk128<MODE>(sb + pc * STG, pc, t, gA, BsRow, xT, R, c8, rb, pj, pyj, pxj);
        asm volatile("cp.async.commit_group;" ::: "memory");
    }

    for (int ch = 0; ch < NC; ch++) {
        asm volatile("cp.async.wait_group 1;" ::: "memory");
        __syncthreads();
        uint32_t stb = sb + (ch % NSTAGE) * STG;

        #pragma unroll
        for (int sub = 0; sub < 2; sub++) {
            uint32_t sA = stb + sub * 16384;
            uint32_t sB = stb + 32768 + sub * 16384;
            #pragma unroll
            for (int kk = 0; kk < 4; kk++) {
                uint32_t ah[4][4], bh[8][2];
                #pragma unroll
                for (int mt = 0; mt < 4; mt++) {
                    int row = wm * 64 + mt * 16 + aRow;
                    ldsm4(ah[mt], sA + row * 128 + (((kk * 2 + aKg) ^ (row & 7)) << 4));
                }
                #pragma unroll
                for (int ng = 0; ng < 4; ng++) {
                    int row = wn * 64 + ng * 16 + bRow;
                    uint32_t r4[4];
                    ldsm4(r4, sB + row * 128 + (((kk * 2 + bKg) ^ (row & 7)) << 4));
                    bh[ng * 2][0] = r4[0]; bh[ng * 2][1] = r4[1];
                    bh[ng * 2 + 1][0] = r4[2]; bh[ng * 2 + 1][1] = r4[3];
                }
                #pragma unroll
                for (int mt = 0; mt < 4; mt++)
                    #pragma unroll
                    for (int nt = 0; nt < 8; nt++)
                        mma16816(acc[mt][nt], ah[mt], bh[nt]);
            }
        }

        int nx = ch + NSTAGE - 1;
        if (nx < NC) {
            load_chunk128<MODE>(sb + (nx % NSTAGE) * STG, nx, t, gA, BsRow, xT,
                                R, c8, rb, pj, pyj, pxj);
        }
        asm volatile("cp.async.commit_group;" ::: "memory");
    }

    // epilogue
    int er = lane >> 2, ec = (lane & 3) * 2;
    #pragma unroll
    for (int mt = 0; mt < 4; mt++) {
        int obase = o0 + wm * 64 + mt * 16 + er;
        #pragma unroll
        for (int h = 0; h < 2; h++) {
            int o = obase + h * 8;
            if (o < Olim) {
                float bv = (bias != nullptr) ? bias[o] : 0.0f;
                size_t rb2 = (size_t)o * o_stride + (size_t)t * t_stride + p0 + wn * 64 + ec;
                #pragma unroll
                for (int nt = 0; nt < 8; nt++) {
                    float2* dp = (float2*)(outp + rb2 + nt * 8);
                    float2 wv;
                    wv.x = acc[mt][nt][h * 2 + 0] + bv;
                    wv.y = acc[mt][nt][h * 2 + 1] + bv;
                    *dp = wv;
                }
            }
        }
    }
}

// ---------------- launch ----------------
extern "C" void kernel_launch(void* const* d_in, const int* in_sizes, int n_in,
                              void* d_out, int out_size) {
    (void)in_sizes; (void)n_in; (void)out_size;
    const float* x      = (const float*)d_in[0];
    const float* w_off  = (const float*)d_in[1];
    const float* w_def  = (const float*)d_in[2];
    const float* w_temp = (const float*)d_in[3];
    const float* b_temp = (const float*)d_in[4];
    float* out = (float*)d_out;

    // Lazy one-time init (first call is the uncaptured correctness run).
    if (g_side == nullptr) {
        cudaStreamCreateWithFlags(&g_side, cudaStreamNonBlocking);
        cudaEventCreateWithFlags(&g_fork, cudaEventDisableTiming);
        cudaEventCreateWithFlags(&g_e1, cudaEventDisableTiming);
        cudaEventCreateWithFlags(&g_e2, cudaEventDisableTiming);
        cudaFuncSetAttribute(gemm_mma<0>, cudaFuncAttributeMaxDynamicSharedMemorySize, GSMEM);
        cudaFuncSetAttribute(gemm_mma<1>, cudaFuncAttributeMaxDynamicSharedMemorySize, GSMEM);
    }

    fp16 *xTp, *Bsp, *wofh, *wfh;
    float* offp;
    cudaGetSymbolAddress((void**)&xTp,  g_xT);
    cudaGetSymbolAddress((void**)&Bsp,  g_Bs);
    cudaGetSymbolAddress((void**)&wofh, g_Woff_h);
    cudaGetSymbolAddress((void**)&wfh,  g_Wf_h);
    cudaGetSymbolAddress((void**)&offp, g_off);

    // fork: weight packs on side stream
    cudaEventRecord(g_fork, 0);
    cudaStreamWaitEvent(g_side, g_fork, 0);
    packw_off<<<dim3(256, 25), 256, 0, g_side>>>(w_off, wofh);
    cudaEventRecord(g_e1, g_side);
    packw_f<<<dim3(256, 52), 256, 0, g_side>>>(w_def, w_temp, wfh);
    cudaEventRecord(g_e2, g_side);

    // main: transpose -> offset GEMM (implicit B) -> sampler -> fused GEMM
    transpose_x<<<dim3(TT, 72, 8), 256>>>(x, xTp);
    cudaStreamWaitEvent(0, g_e1, 0);
    gemm_mma<0><<<dim3(18, TT, 2), 128, GSMEM>>>(
        wofh, xTp /*unused explicit*/, xTp, offp, R5, OFFC,
        PP, (long long)OFFC * PP, nullptr);

    sample_k<<<dim3(TT, 72, 4), 256>>>(xTp, offp, Bsp);

    cudaStreamWaitEvent(0, g_e2, 0);
    gemm_mma<1><<<dim3(18, TT, 2), 128, GSMEM>>>(
        wfh, Bsp, xTp, out, RF, 256, (long long)TT * PP, PP, b_temp);
}

// round 15
// speedup vs baseline: 1.1276x; 1.0710x over previous
#include <cuda_runtime.h>
#include <cuda_fp16.h>
#include <cstdint>

#define TT   4
#define HH   48
#define WWD  48
#define PP   2304          // 48*48
#define R5   6400          // 256*25
#define R3   6912          // 256*27
#define OFFC 200           // 4*2*25

typedef __half fp16;

// ---------------- scratch (static device globals; no allocation) ----------------
__device__ fp16 g_xT[(size_t)TT * PP * 256];  // [t][p][c] fp16 transpose of x (L2-resident)
__device__ fp16 g_Bs[(size_t)TT * PP * R5];   // [t][p][k*256+c] sampled B (k-major)
__device__ fp16 g_Woff[256 * R5];             // [o][k*256+c], padded O
__device__ fp16 g_Wdef[256 * R5];             // [o][k*256+c]
__device__ fp16 g_Wtmp[256 * R3];             // [o][q*256+c]
__device__ float g_off[TT * OFFC * PP];       // [t][och][p]

// ---------------- side stream: LAZY init on first kernel_launch (never in static ctor —
// pre-main CUDA calls latch error 802 "system not yet initialized" on GB300) ----------------
static cudaStream_t g_side = nullptr;
static cudaEvent_t g_fork, g_e1, g_e2, g_eG0, g_eS;

// ---------------- helpers ----------------
__device__ __forceinline__ uint32_t smem_u32(const void* p) {
    uint32_t a;
    asm("{ .reg .u64 t; cvta.to.shared.u64 t, %1; cvt.u32.u64 %0, t; }" : "=r"(a) : "l"(p));
    return a;
}
__device__ __forceinline__ void cpa16(uint32_t dst, const void* src) {
    asm volatile("cp.async.cg.shared.global [%0], [%1], 16;" :: "r"(dst), "l"(src) : "memory");
}
__device__ __forceinline__ void cpa16z(uint32_t dst, const void* src, int vld16) {
    asm volatile("cp.async.cg.shared.global [%0], [%1], 16, %2;"
                 :: "r"(dst), "l"(src), "r"(vld16) : "memory");
}
__device__ __forceinline__ void ldsm4(uint32_t* r, uint32_t a) {
    asm volatile("ldmatrix.sync.aligned.m8n8.x4.shared.b16 {%0,%1,%2,%3}, [%4];"
                 : "=r"(r[0]), "=r"(r[1]), "=r"(r[2]), "=r"(r[3]) : "r"(a));
}
__device__ __forceinline__ void mma16816(float* c, const uint32_t* a, const uint32_t* b) {
    asm volatile("mma.sync.aligned.m16n8k16.row.col.f32.f16.f16.f32 "
                 "{%0,%1,%2,%3}, {%4,%5,%6,%7}, {%8,%9}, {%0,%1,%2,%3};"
                 : "+f"(c[0]), "+f"(c[1]), "+f"(c[2]), "+f"(c[3])
                 : "r"(a[0]), "r"(a[1]), "r"(a[2]), "r"(a[3]), "r"(b[0]), "r"(b[1]));
}

// ---------------- x transpose: x[c][t][p] fp32 -> xT[t][p][c] fp16 ----------------
__global__ void __launch_bounds__(256) transpose_x(const float* __restrict__ x,
                                                   fp16* __restrict__ xT) {
    __shared__ float tl[32][33];
    int t = blockIdx.x, p0 = blockIdx.y * 32, c0 = blockIdx.z * 32;
    int tx = threadIdx.x & 31, ty = threadIdx.x >> 5;
    #pragma unroll
    for (int i = ty; i < 32; i += 8)
        tl[i][tx] = x[((size_t)(c0 + i) * TT + t) * PP + p0 + tx];
    __syncthreads();
    #pragma unroll
    for (int i = ty; i < 32; i += 8)
        xT[((size_t)t * PP + p0 + i) * 256 + c0 + tx] = __float2half_rn(tl[tx][i]);
}

// ---------------- weight packs: [o][c][k] -> [o][k*256+c] fp16 ----------------
__global__ void packw_off(const float* __restrict__ src, fp16* __restrict__ h) {
    int o = blockIdx.x;
    int r = blockIdx.y * 256 + threadIdx.x;
    int c = r & 255, k = r >> 8;
    float v = (o < OFFC) ? src[((size_t)o * 256 + c) * 25 + k] : 0.0f;
    h[(size_t)o * R5 + r] = __float2half_rn(v);
}
__global__ void packw_def(const float* __restrict__ src, fp16* __restrict__ h) {
    int o = blockIdx.x;
    int r = blockIdx.y * 256 + threadIdx.x;
    int c = r & 255, k = r >> 8;
    h[(size_t)o * R5 + r] = __float2half_rn(src[((size_t)o * 256 + c) * 25 + k]);
}
__global__ void packw_tmp(const float* __restrict__ src, fp16* __restrict__ h) {
    int o = blockIdx.x;
    int r = blockIdx.y * 256 + threadIdx.x;
    int c = r & 255, q = r >> 8;
    h[(size_t)o * R3 + r] = __float2half_rn(src[((size_t)o * 256 + c) * 27 + q]);
}

// ---------------- bilinear sampler on xT -> Bs[t][p][k*256+c] ----------------
__global__ void __launch_bounds__(256) sample_k(const fp16* __restrict__ xT,
                                                const float* __restrict__ off,
                                                fp16* __restrict__ Bs) {
    int t = blockIdx.x, p0 = blockIdx.y * 32, dg = blockIdx.z;
    int oct = threadIdx.x & 7, pl = threadIdx.x >> 3;
    int p = p0 + pl, py = p / WWD, px = p % WWD;
    const fp16* xb = xT + (size_t)t * PP * 256 + dg * 64 + oct * 8;
    fp16* dstb = Bs + ((size_t)t * PP + p) * R5 + dg * 64 + oct * 8;
    #pragma unroll 1
    for (int k = 0; k < 25; k++) {
        const float* offy = off + ((size_t)t * OFFC + (dg * 25 + k) * 2) * PP;
        float sy = (float)(py + k / 5 - 2) + __ldg(offy + p);
        float sx = (float)(px + k % 5 - 2) + __ldg(offy + PP + p);
        float fy = floorf(sy), fx = floorf(sx);
        int y0 = (int)fy, x0 = (int)fx;
        float wy = sy - fy, wx = sx - fx;
        int y1 = y0 + 1, x1 = x0 + 1;
        float vy0 = (y0 >= 0 && y0 < HH) ? 1.0f : 0.0f;
        float vy1 = (y1 >= 0 && y1 < HH) ? 1.0f : 0.0f;
        float vx0 = (x0 >= 0 && x0 < WWD) ? 1.0f : 0.0f;
        float vx1 = (x1 >= 0 && x1 < WWD) ? 1.0f : 0.0f;
        int y0c = min(max(y0, 0), HH - 1), y1c = min(max(y1, 0), HH - 1);
        int x0c = min(max(x0, 0), WWD - 1), x1c = min(max(x1, 0), WWD - 1);
        float w00 = (1.0f - wy) * (1.0f - wx) * vy0 * vx0;
        float w01 = (1.0f - wy) * wx          * vy0 * vx1;
        float w10 = wy          * (1.0f - wx) * vy1 * vx0;
        float w11 = wy          * wx          * vy1 * vx1;
        const __half2* a = (const __half2*)(xb + (size_t)(y0c * WWD + x0c) * 256);
        const __half2* b = (const __half2*)(xb + (size_t)(y0c * WWD + x1c) * 256);
        const __half2* cq = (const __half2*)(xb + (size_t)(y1c * WWD + x0c) * 256);
        const __half2* d = (const __half2*)(xb + (size_t)(y1c * WWD + x1c) * 256);
        __half2 r[4];
        #pragma unroll
        for (int j = 0; j < 4; j++) {
            float2 fa = __half22float2(a[j]), fb = __half22float2(b[j]);
            float2 fc = __half22float2(cq[j]), fd = __half22float2(d[j]);
            float rx = w00 * fa.x + w01 * fb.x + w10 * fc.x + w11 * fd.x;
            float ry = w00 * fa.y + w01 * fb.y + w10 * fc.y + w11 * fd.y;
            r[j] = __floats2half2_rn(rx, ry);
        }
        *(uint4*)(dstb + k * 256) = *(uint4*)r;
    }
}

// ---------------- GEMM: tile 128(o) x 128(p), 4 warps, warp tile 64x64 ----------------
// K chunk 128 = two 64-K sub-tiles per stage (A0,A1,B0,B1 = 64KB/stage), 3 stages (192KB).
// MODE 0: offset conv — B implicit 1x5x5 from xT (K=R5), write.
// MODE 1: deform    — B explicit from Bs (K=R5), ACCUMULATE into out.
// MODE 2: temporal  — B implicit 3x3x3 from xT (K=R3), write + bias.
#define NSTAGE 3
#define STG    65536
#define GSMEM  (NSTAGE * STG)

template<int MODE>
__device__ __forceinline__ void loadB64(
    uint32_t dstB, int m64, int t, const fp16* __restrict__ BsRow,
    const fp16* __restrict__ xT, int c8, int rb,
    const int* pj, const int* pyj, const int* pxj)
{
    if (MODE == 1) {
        size_t rof = (size_t)m64 * 64 + c8 * 8;
        #pragma unroll
        for (int j = 0; j < 8; j++) {
            int row = rb + 16 * j;
            cpa16(dstB + row * 128 + ((c8 ^ (row & 7)) << 4),
                  BsRow + (size_t)row * R5 + rof);
        }
    } else {
        int kk = m64 >> 2, c0 = (m64 & 3) * 64;
        int dy, dx, tt;
        if (MODE == 0) { dy = kk / 5 - 2; dx = kk % 5 - 2; tt = t; }
        else { tt = t + kk / 9 - 1; int rq = kk % 9; dy = rq / 3 - 1; dx = rq % 3 - 1; }
        int tok = (tt >= 0 && tt < TT) ? 1 : 0;
        #pragma unroll
        for (int j = 0; j < 8; j++) {
            int row = rb + 16 * j;
            int y = pyj[j] + dy, x = pxj[j] + dx;
            int vld = (tok && y >= 0 && y < HH && x >= 0 && x < WWD) ? 16 : 0;
            size_t soff = vld ? ((size_t)(tt * PP + pj[j] + dy * WWD + dx) * 256
                                 + c0 + c8 * 8) : 0;
            cpa16z(dstB + row * 128 + ((c8 ^ (row & 7)) << 4), xT + soff, vld);
        }
    }
}

template<int MODE>
__device__ __forceinline__ void load_chunk128(
    uint32_t stb, int ch, int t, const fp16* __restrict__ gA,
    const fp16* __restrict__ BsRow, const fp16* __restrict__ xT,
    int R, int c8, int rb, const int* pj, const int* pyj, const int* pxj)
{
    #pragma unroll
    for (int sub = 0; sub < 2; sub++) {
        int m64 = ch * 2 + sub;
        size_t rof = (size_t)m64 * 64 + c8 * 8;
        uint32_t sA = stb + sub * 16384;
        #pragma unroll
        for (int j = 0; j < 8; j++) {
            int row = rb + 16 * j;
            cpa16(sA + row * 128 + ((c8 ^ (row & 7)) << 4), gA + (size_t)row * R + rof);
        }
        loadB64<MODE>(stb + 32768 + sub * 16384, m64, t, BsRow, xT, c8, rb, pj, pyj, pxj);
    }
}

template<int MODE>
__global__ void __launch_bounds__(128, 1) gemm_mma(
    const fp16* __restrict__ Wh, const fp16* __restrict__ Bs,
    const fp16* __restrict__ xT,
    float* __restrict__ outp, int R, int Olim,
    long long o_stride, long long t_stride,
    const float* __restrict__ bias)
{
    extern __shared__ char smraw[];
    uint32_t sb = smem_u32(smraw);
    int tid = threadIdx.x, lane = tid & 31, wid = tid >> 5;
    int wm = wid & 1, wn = wid >> 1;               // 2 x 2 -> warp tile 64(m) x 64(n)
    int p0 = blockIdx.x * 128, t = blockIdx.y, o0 = blockIdx.z * 128;

    const fp16* gA = Wh + (size_t)o0 * R;
    const fp16* BsRow = Bs + ((size_t)t * PP + p0) * R5;

    int c8 = tid & 7;
    int rb = tid >> 3;             // 0..15
    int NC = R >> 7;               // 128-K chunks

    int pj[8], pyj[8], pxj[8];
    #pragma unroll
    for (int j = 0; j < 8; j++) {
        pj[j] = p0 + rb + 16 * j;
        pyj[j] = pj[j] / WWD;
        pxj[j] = pj[j] % WWD;
    }

    int aRow = (lane & 7) + ((lane >> 3) & 1) * 8;
    int aKg  = (lane >> 4) & 1;
    int bRow = (lane & 7) + ((lane >> 4) & 1) * 8;
    int bKg  = (lane >> 3) & 1;

    float acc[4][8][4];
    #pragma unroll
    for (int i = 0; i < 4; i++)
        #pragma unroll
        for (int j = 0; j < 8; j++)
            #pragma unroll
            for (int q = 0; q < 4; q++) acc[i][j][q] = 0.0f;

    // prologue: chunks 0,1
    #pragma unroll
    for (int pc = 0; pc < NSTAGE - 1; pc++) {
        load_chunk128<MODE>(sb + pc * STG, pc, t, gA, BsRow, xT, R, c8, rb, pj, pyj, pxj);
        asm volatile("cp.async.commit_group;" ::: "memory");
    }

    for (int ch = 0; ch < NC; ch++) {
        asm volatile("cp.async.wait_group 1;" ::: "memory");
        __syncthreads();
        uint32_t stb = sb + (ch % NSTAGE) * STG;

        #pragma unroll
        for (int sub = 0; sub < 2; sub++) {
            uint32_t sA = stb + sub * 16384;
            uint32_t sB = stb + 32768 + sub * 16384;
            #pragma unroll
            for (int kk = 0; kk < 4; kk++) {
                uint32_t ah[4][4], bh[8][2];
                #pragma unroll
                for (int mt = 0; mt < 4; mt++) {
                    int row = wm * 64 + mt * 16 + aRow;
                    ldsm4(ah[mt], sA + row * 128 + (((kk * 2 + aKg) ^ (row & 7)) << 4));
                }
                #pragma unroll
                for (int ng = 0; ng < 4; ng++) {
                    int row = wn * 64 + ng * 16 + bRow;
                    uint32_t r4[4];
                    ldsm4(r4, sB + row * 128 + (((kk * 2 + bKg) ^ (row & 7)) << 4));
                    bh[ng * 2][0] = r4[0]; bh[ng * 2][1] = r4[1];
                    bh[ng * 2 + 1][0] = r4[2]; bh[ng * 2 + 1][1] = r4[3];
                }
                #pragma unroll
                for (int mt = 0; mt < 4; mt++)
                    #pragma unroll
                    for (int nt = 0; nt < 8; nt++)
                        mma16816(acc[mt][nt], ah[mt], bh[nt]);
            }
        }

        int nx = ch + NSTAGE - 1;
        if (nx < NC) {
            load_chunk128<MODE>(sb + (nx % NSTAGE) * STG, nx, t, gA, BsRow, xT,
                                R, c8, rb, pj, pyj, pxj);
        }
        asm volatile("cp.async.commit_group;" ::: "memory");
    }

    // epilogue (MODE 1 accumulates into out)
    int er = lane >> 2, ec = (lane & 3) * 2;
    #pragma unroll
    for (int mt = 0; mt < 4; mt++) {
        int obase = o0 + wm * 64 + mt * 16 + er;
        #pragma unroll
        for (int h = 0; h < 2; h++) {
            int o = obase + h * 8;
            if (o < Olim) {
                float bv = (bias != nullptr) ? bias[o] : 0.0f;
                size_t rb2 = (size_t)o * o_stride + (size_t)t * t_stride + p0 + wn * 64 + ec;
                #pragma unroll
                for (int nt = 0; nt < 8; nt++) {
                    float2* dp = (float2*)(outp + rb2 + nt * 8);
                    float2 wv;
                    wv.x = acc[mt][nt][h * 2 + 0] + bv;
                    wv.y = acc[mt][nt][h * 2 + 1] + bv;
                    if (MODE == 1) { float2 old = *dp; wv.x += old.x; wv.y += old.y; }
                    *dp = wv;
                }
            }
        }
    }
}

// ---------------- launch ----------------
extern "C" void kernel_launch(void* const* d_in, const int* in_sizes, int n_in,
                              void* d_out, int out_size) {
    (void)in_sizes; (void)n_in; (void)out_size;
    const float* x      = (const float*)d_in[0];
    const float* w_off  = (const float*)d_in[1];
    const float* w_def  = (const float*)d_in[2];
    const float* w_temp = (const float*)d_in[3];
    const float* b_temp = (const float*)d_in[4];
    float* out = (float*)d_out;

    // Lazy one-time init (first call is the uncaptured correctness run).
    if (g_side == nullptr) {
        cudaStreamCreateWithFlags(&g_side, cudaStreamNonBlocking);
        cudaEventCreateWithFlags(&g_fork, cudaEventDisableTiming);
        cudaEventCreateWithFlags(&g_e1, cudaEventDisableTiming);
        cudaEventCreateWithFlags(&g_e2, cudaEventDisableTiming);
        cudaEventCreateWithFlags(&g_eG0, cudaEventDisableTiming);
        cudaEventCreateWithFlags(&g_eS, cudaEventDisableTiming);
        cudaFuncSetAttribute(gemm_mma<0>, cudaFuncAttributeMaxDynamicSharedMemorySize, GSMEM);
        cudaFuncSetAttribute(gemm_mma<1>, cudaFuncAttributeMaxDynamicSharedMemorySize, GSMEM);
        cudaFuncSetAttribute(gemm_mma<2>, cudaFuncAttributeMaxDynamicSharedMemorySize, GSMEM);
    }

    fp16 *xTp, *Bsp, *woffp, *wdefp, *wtmpp;
    float* offp;
    cudaGetSymbolAddress((void**)&xTp,   g_xT);
    cudaGetSymbolAddress((void**)&Bsp,   g_Bs);
    cudaGetSymbolAddress((void**)&woffp, g_Woff);
    cudaGetSymbolAddress((void**)&wdefp, g_Wdef);
    cudaGetSymbolAddress((void**)&wtmpp, g_Wtmp);
    cudaGetSymbolAddress((void**)&offp,  g_off);

    // fork: weight packs + (later) sampler on side stream
    cudaEventRecord(g_fork, 0);
    cudaStreamWaitEvent(g_side, g_fork, 0);
    packw_off<<<dim3(256, 25), 256, 0, g_side>>>(w_off, woffp);
    cudaEventRecord(g_e1, g_side);
    packw_tmp<<<dim3(256, 27), 256, 0, g_side>>>(w_temp, wtmpp);
    cudaEventRecord(g_e2, g_side);
    packw_def<<<dim3(256, 25), 256, 0, g_side>>>(w_def, wdefp);

    // main: transpose -> offset GEMM (implicit 5x5 B)
    transpose_x<<<dim3(TT, 72, 8), 256>>>(x, xTp);
    cudaStreamWaitEvent(0, g_e1, 0);
    gemm_mma<0><<<dim3(18, TT, 2), 128, GSMEM>>>(
        woffp, Bsp /*unused*/, xTp, offp, R5, OFFC,
        PP, (long long)OFFC * PP, nullptr);
    cudaEventRecord(g_eG0, 0);

    // side: sampler (needs offsets) — overlaps with temporal GEMM on main
    cudaStreamWaitEvent(g_side, g_eG0, 0);
    sample_k<<<dim3(TT, 72, 4), 256, 0, g_side>>>(xTp, offp, Bsp);
    cudaEventRecord(g_eS, g_side);

    // main: temporal GEMM (implicit 3x3x3, independent of sampler), writes out + bias
    cudaStreamWaitEvent(0, g_e2, 0);
    gemm_mma<2><<<dim3(18, TT, 2), 128, GSMEM>>>(
        wtmpp, Bsp /*unused*/, xTp, out, R3, 256,
        (long long)TT * PP, PP, b_temp);

    // main: deform GEMM (explicit Bs), accumulates into out
    cudaStreamWaitEvent(0, g_eS, 0);
    gemm_mma<1><<<dim3(18, TT, 2), 128, GSMEM>>>(
        wdefp, Bsp, xTp, out, R5, 256,
        (long long)TT * PP, PP, nullptr);
}